// round 9
// baseline (speedup 1.0000x reference)
#include <cuda_runtime.h>
#include <cuda_bf16.h>
#include <cstdint>

// NGFTextureFetch — bilinear sampling of per-complex feature maps.
// map: [2048, 16, 16, 64] f32 (64 KB/complex), u,v: [2048, 256] f32
// out: [2048, 256, 64] f32
//
// Persistent-CTA, TRIPLE-buffered cp.async.bulk pipeline:
//   - 148 CTAs x 512 threads, one CTA/SM, ~14 complexes each.
//   - 3 smem buffers (map+u+v = 67584 B each, 202752 B total): two loads are
//     always in flight while warps bilerp+store the current complex, so each
//     66KB load has ~2 compute windows to complete -> mbar_wait never blocks.
//   - Output uses streaming stores (__stcs) to keep L2 for the read stream.

#define NC   2048
#define RH   16
#define RW   16
#define NF   64
#define NP   256
#define TPB  512
#define GRID 148
#define NBUF 3

#define MAP_BYTES (RH * RW * NF * 4)          // 65536
#define UV_BYTES  (NP * 4)                    // 1024
#define BUF_BYTES (MAP_BYTES + 2 * UV_BYTES)  // 67584
#define SMEM_DYN  (NBUF * BUF_BYTES)          // 202752

__device__ __forceinline__ uint32_t smem_u32(const void* p) {
    return (uint32_t)__cvta_generic_to_shared(p);
}

__device__ __forceinline__ void bulk_copy_g2s(uint32_t dst, const void* src,
                                              uint32_t bytes, uint32_t mbar) {
    asm volatile(
        "cp.async.bulk.shared::cta.global.mbarrier::complete_tx::bytes "
        "[%0], [%1], %2, [%3];"
        :: "r"(dst), "l"(src), "r"(bytes), "r"(mbar) : "memory");
}

__device__ __forceinline__ void mbar_wait(uint32_t mbar, uint32_t parity) {
    uint32_t done;
    do {
        asm volatile(
            "{\n\t.reg .pred p;\n\t"
            "mbarrier.try_wait.parity.shared.b64 p, [%1], %2;\n\t"
            "selp.b32 %0, 1, 0, p;\n\t}"
            : "=r"(done) : "r"(mbar), "r"(parity) : "memory");
    } while (!done);
}

__global__ __launch_bounds__(TPB, 1)
void ngf_persistent_kernel(const float* __restrict__ map,
                           const float* __restrict__ u,
                           const float* __restrict__ v,
                           float* __restrict__ out)
{
    extern __shared__ __align__(128) unsigned char smem[];
    __shared__ __align__(8) uint64_t mbar_s[NBUF];

    const int tid = threadIdx.x;
    const int cta = blockIdx.x;

    if (tid == 0) {
        #pragma unroll
        for (int s = 0; s < NBUF; ++s)
            asm volatile("mbarrier.init.shared.b64 [%0], 1;"
                         :: "r"(smem_u32(&mbar_s[s])));
        asm volatile("fence.proxy.async.shared::cta;" ::: "memory");
    }
    __syncthreads();

    // complexes handled by this CTA: c = cta + k * GRID
    const int n_my = (NC - cta + GRID - 1) / GRID;

    auto issue = [&](int k) {
        const int slot = k % NBUF;
        const int c = cta + k * GRID;
        const uint32_t mb  = smem_u32(&mbar_s[slot]);
        const uint32_t dst = smem_u32(smem) + slot * BUF_BYTES;
        asm volatile(
            "mbarrier.arrive.expect_tx.shared.b64 _, [%0], %1;"
            :: "r"(mb), "r"((uint32_t)BUF_BYTES) : "memory");
        const char* gm = (const char*)(map + (size_t)c * (RH * RW * NF));
        #pragma unroll
        for (int q = 0; q < 4; ++q)
            bulk_copy_g2s(dst + q * 16384, gm + q * 16384, 16384, mb);
        bulk_copy_g2s(dst + MAP_BYTES,            u + (size_t)c * NP, UV_BYTES, mb);
        bulk_copy_g2s(dst + MAP_BYTES + UV_BYTES, v + (size_t)c * NP, UV_BYTES, mb);
    };

    if (tid == 0) {
        issue(0);
        if (n_my > 1) issue(1);
        if (n_my > 2) issue(2);
    }

    for (int k = 0; k < n_my; ++k) {
        const int slot = k % NBUF;
        const uint32_t parity = (uint32_t)(k / NBUF) & 1u;
        mbar_wait(smem_u32(&mbar_s[slot]), parity);

        const float4* smap = (const float4*)(smem + slot * BUF_BYTES);
        const float*  su   = (const float*)(smem + slot * BUF_BYTES + MAP_BYTES);
        const float*  sv   = su + NP;

        const int c = cta + k * GRID;
        float4* outc = (float4*)(out + (size_t)c * (NP * NF));

        #pragma unroll 4
        for (int i = 0; i < 8; ++i) {
            const int task = i * TPB + tid;     // 0..4095
            const int p    = task >> 4;         // sample index
            const int f4i  = task & 15;         // float4 lane within 64 feats

            const float x = su[p] * (float)(RW - 1);
            const float y = sv[p] * (float)(RH - 1);
            int x0 = (int)floorf(x);
            int y0 = (int)floorf(y);
            x0 = min(max(x0, 0), RW - 2);
            y0 = min(max(y0, 0), RH - 2);
            const float fx = x - (float)x0;
            const float fy = y - (float)y0;
            const float wx0 = 1.0f - fx, wx1 = fx;
            const float wy0 = 1.0f - fy, wy1 = fy;

            const float4* g = smap + ((y0 * RW + x0) << 4) + f4i;
            const float4 a  = g[0];                 // (y0,   x0)
            const float4 b  = g[16];                // (y0,   x0+1)
            const float4 cc = g[RW * 16];           // (y0+1, x0)
            const float4 d  = g[(RW + 1) * 16];     // (y0+1, x0+1)

            float4 r;
            r.x = (a.x * wx0 + b.x * wx1) * wy0 + (cc.x * wx0 + d.x * wx1) * wy1;
            r.y = (a.y * wx0 + b.y * wx1) * wy0 + (cc.y * wx0 + d.y * wx1) * wy1;
            r.z = (a.z * wx0 + b.z * wx1) * wy0 + (cc.z * wx0 + d.z * wx1) * wy1;
            r.w = (a.w * wx0 + b.w * wx1) * wy0 + (cc.w * wx0 + d.w * wx1) * wy1;

            __stcs(&outc[task], r);             // streaming store: evict-first
        }

        __syncthreads();                        // buf[slot] fully consumed
        if (tid == 0 && k + NBUF < n_my)
            issue(k + NBUF);                    // refill freed buffer
    }
}

extern "C" void kernel_launch(void* const* d_in, const int* in_sizes, int n_in,
                              void* d_out, int out_size)
{
    const float* map = (const float*)d_in[0];
    const float* u   = (const float*)d_in[1];
    const float* v   = (const float*)d_in[2];
    float* out       = (float*)d_out;

    cudaFuncSetAttribute(ngf_persistent_kernel,
                         cudaFuncAttributeMaxDynamicSharedMemorySize, SMEM_DYN);

    ngf_persistent_kernel<<<GRID, TPB, SMEM_DYN>>>(map, u, v, out);
}

// round 10
// speedup vs baseline: 1.0461x; 1.0461x over previous
#include <cuda_runtime.h>
#include <cuda_bf16.h>
#include <cstdint>

// NGFTextureFetch — bilinear sampling of per-complex feature maps.
// map: [2048, 16, 16, 64] f32 (64 KB/complex), u,v: [2048, 256] f32
// out: [2048, 256, 64] f32
//
// Warp-specialized persistent pipeline (no CTA-wide barrier in the loop):
//   - 148 CTAs (1/SM). 16 compute warps + 1 producer warp.
//   - 3 smem buffers. full[s] = TMA tx mbarrier; empty[s] = count-16 mbarrier,
//     one arrive per compute warp when it finishes reading buffer s.
//   - Producer issues the refill the instant the last warp releases the
//     buffer; compute warps drift independently across complexes, keeping
//     the DRAM read (TMA) and write (STG.128 streaming) streams smooth.

#define NC   2048
#define RH   16
#define RW   16
#define NF   64
#define NP   256
#define NWRP 16                 // compute warps
#define TPB  (NWRP * 32 + 32)   // + producer warp = 544
#define GRID 148
#define NBUF 3

#define MAP_BYTES (RH * RW * NF * 4)          // 65536
#define UV_BYTES  (NP * 4)                    // 1024
#define BUF_BYTES (MAP_BYTES + 2 * UV_BYTES)  // 67584
#define SMEM_DYN  (NBUF * BUF_BYTES)          // 202752

__device__ __forceinline__ uint32_t smem_u32(const void* p) {
    return (uint32_t)__cvta_generic_to_shared(p);
}

__device__ __forceinline__ void bulk_copy_g2s(uint32_t dst, const void* src,
                                              uint32_t bytes, uint32_t mbar) {
    asm volatile(
        "cp.async.bulk.shared::cta.global.mbarrier::complete_tx::bytes "
        "[%0], [%1], %2, [%3];"
        :: "r"(dst), "l"(src), "r"(bytes), "r"(mbar) : "memory");
}

__device__ __forceinline__ void mbar_wait(uint32_t mbar, uint32_t parity) {
    uint32_t done;
    do {
        asm volatile(
            "{\n\t.reg .pred p;\n\t"
            "mbarrier.try_wait.parity.shared.b64 p, [%1], %2, 0x989680;\n\t"
            "selp.b32 %0, 1, 0, p;\n\t}"
            : "=r"(done) : "r"(mbar), "r"(parity) : "memory");
    } while (!done);
}

__global__ __launch_bounds__(TPB, 1)
void ngf_ws_kernel(const float* __restrict__ map,
                   const float* __restrict__ u,
                   const float* __restrict__ v,
                   float* __restrict__ out)
{
    extern __shared__ __align__(128) unsigned char smem[];
    __shared__ __align__(8) uint64_t full_s[NBUF];
    __shared__ __align__(8) uint64_t empty_s[NBUF];

    const int tid = threadIdx.x;
    const int cta = blockIdx.x;

    if (tid == 0) {
        #pragma unroll
        for (int s = 0; s < NBUF; ++s) {
            asm volatile("mbarrier.init.shared.b64 [%0], 1;"
                         :: "r"(smem_u32(&full_s[s])));
            asm volatile("mbarrier.init.shared.b64 [%0], %1;"
                         :: "r"(smem_u32(&empty_s[s])), "r"(NWRP));
        }
        asm volatile("fence.proxy.async.shared::cta;" ::: "memory");
    }
    __syncthreads();   // barriers visible to all; only sync in the kernel

    // complexes handled by this CTA: c = cta + k * GRID
    const int n_my = (NC - cta + GRID - 1) / GRID;

    if (tid >= NWRP * 32) {
        // ---------------- producer warp ----------------
        if (tid == NWRP * 32) {
            for (int k = 0; k < n_my; ++k) {
                const int slot = k % NBUF;
                const int j    = k / NBUF;          // occurrence of this slot
                if (j > 0)                          // wait slot released
                    mbar_wait(smem_u32(&empty_s[slot]), (uint32_t)(j - 1) & 1u);

                const int c = cta + k * GRID;
                const uint32_t mb  = smem_u32(&full_s[slot]);
                const uint32_t dst = smem_u32(smem) + slot * BUF_BYTES;
                asm volatile(
                    "mbarrier.arrive.expect_tx.shared.b64 _, [%0], %1;"
                    :: "r"(mb), "r"((uint32_t)BUF_BYTES) : "memory");
                const char* gm = (const char*)(map + (size_t)c * (RH * RW * NF));
                #pragma unroll
                for (int q = 0; q < 4; ++q)
                    bulk_copy_g2s(dst + q * 16384, gm + q * 16384, 16384, mb);
                bulk_copy_g2s(dst + MAP_BYTES,            u + (size_t)c * NP, UV_BYTES, mb);
                bulk_copy_g2s(dst + MAP_BYTES + UV_BYTES, v + (size_t)c * NP, UV_BYTES, mb);
            }
        }
        return;
    }

    // ---------------- compute warps (tid 0..511) ----------------
    const int lane = tid & 31;

    for (int k = 0; k < n_my; ++k) {
        const int slot = k % NBUF;
        const uint32_t parity = (uint32_t)(k / NBUF) & 1u;
        mbar_wait(smem_u32(&full_s[slot]), parity);

        const float4* smap = (const float4*)(smem + slot * BUF_BYTES);
        const float*  su   = (const float*)(smem + slot * BUF_BYTES + MAP_BYTES);
        const float*  sv   = su + NP;

        const int c = cta + k * GRID;
        float4* outc = (float4*)(out + (size_t)c * (NP * NF));

        #pragma unroll 4
        for (int i = 0; i < 8; ++i) {
            const int task = i * (NWRP * 32) + tid;  // 0..4095
            const int p    = task >> 4;              // sample index
            const int f4i  = task & 15;              // float4 lane within feats

            const float x = su[p] * (float)(RW - 1);
            const float y = sv[p] * (float)(RH - 1);
            int x0 = (int)floorf(x);
            int y0 = (int)floorf(y);
            x0 = min(max(x0, 0), RW - 2);
            y0 = min(max(y0, 0), RH - 2);
            const float fx = x - (float)x0;
            const float fy = y - (float)y0;
            const float wx0 = 1.0f - fx, wx1 = fx;
            const float wy0 = 1.0f - fy, wy1 = fy;

            const float4* g = smap + ((y0 * RW + x0) << 4) + f4i;
            const float4 a  = g[0];                 // (y0,   x0)
            const float4 b  = g[16];                // (y0,   x0+1)
            const float4 cc = g[RW * 16];           // (y0+1, x0)
            const float4 d  = g[(RW + 1) * 16];     // (y0+1, x0+1)

            float4 r;
            r.x = (a.x * wx0 + b.x * wx1) * wy0 + (cc.x * wx0 + d.x * wx1) * wy1;
            r.y = (a.y * wx0 + b.y * wx1) * wy0 + (cc.y * wx0 + d.y * wx1) * wy1;
            r.z = (a.z * wx0 + b.z * wx1) * wy0 + (cc.z * wx0 + d.z * wx1) * wy1;
            r.w = (a.w * wx0 + b.w * wx1) * wy0 + (cc.w * wx0 + d.w * wx1) * wy1;

            __stcs(&outc[task], r);                 // streaming store
        }

        // this warp is done reading buf[slot] — release it (1 of 16 arrives)
        if (lane == 0)
            asm volatile("mbarrier.arrive.shared.b64 _, [%0];"
                         :: "r"(smem_u32(&empty_s[slot])) : "memory");
    }
}

extern "C" void kernel_launch(void* const* d_in, const int* in_sizes, int n_in,
                              void* d_out, int out_size)
{
    const float* map = (const float*)d_in[0];
    const float* u   = (const float*)d_in[1];
    const float* v   = (const float*)d_in[2];
    float* out       = (float*)d_out;

    cudaFuncSetAttribute(ngf_ws_kernel,
                         cudaFuncAttributeMaxDynamicSharedMemorySize, SMEM_DYN);

    ngf_ws_kernel<<<GRID, TPB, SMEM_DYN>>>(map, u, v, out);
}